// round 2
// baseline (speedup 1.0000x reference)
#include <cuda_runtime.h>
#include <math.h>

#define T_ 256
#define B_ 8
#define D_ 128
#define L_ 2
#define ROWS (B_*T_)                  // 2048
#define STROW (L_*(D_*D_+D_)+1)       // 33025
#define YSZ (T_*B_*D_)                // 262144

// ---------------- scratch (device globals; no allocation allowed) ----------
__device__ float g_x  [ROWS*D_];
__device__ float g_xln[ROWS*D_];
__device__ float g_Q  [ROWS*D_];
__device__ float g_K  [ROWS*D_];
__device__ float g_V  [ROWS*D_];
__device__ float g_A  [B_*T_*T_];
__device__ float g_att[ROWS*D_];
__device__ float g_h1 [ROWS*D_];
__device__ float g_t2 [ROWS*D_];

// ---------------- rotate (RoPE) + transpose z(T,B,D)->x(B,T,D) -------------
__global__ void rotate_kernel(const float* __restrict__ z,
                              const float* __restrict__ state,
                              float* __restrict__ x,
                              float* __restrict__ out_st)
{
    int idx = blockIdx.x * blockDim.x + threadIdx.x;   // B*T*64
    if (idx >= B_*T_*64) return;
    int j = idx & 63;
    int t = (idx >> 6) % T_;
    int b = idx / (64 * T_);
    float ts  = state[b*STROW + (STROW-1)];
    float pos = ts + (float)t;
    float freq = expf((float)(2*j) * (-logf(10000.0f) / (float)D_));
    float ang = pos * freq;
    float s, c;
    sincosf(ang, &s, &c);
    const float* zr = z + ((size_t)t*B_ + b) * D_;
    float*       xr = x + ((size_t)b*T_ + t) * D_;
    float a0 = zr[j], a1 = zr[j+64];
    xr[j]    = a0*c - a1*s;
    xr[j+64] = a1*c + a0*s;
    if (t == 0 && j == 0)
        out_st[b*STROW + (STROW-1)] = ts + (float)T_;
}

// ---------------- layernorm, one block (128 thr) per row --------------------
__global__ void ln_kernel(const float* __restrict__ x,
                          const float* __restrict__ w,
                          const float* __restrict__ b,
                          float* __restrict__ y)
{
    int row = blockIdx.x;
    int j = threadIdx.x;
    float v = x[row*D_ + j];
    __shared__ float sh[4], sh2[4];
    float s = v;
    #pragma unroll
    for (int o = 16; o; o >>= 1) s += __shfl_xor_sync(~0u, s, o);
    if ((j & 31) == 0) sh[j >> 5] = s;
    __syncthreads();
    float m = (sh[0] + sh[1] + sh[2] + sh[3]) * (1.0f/128.0f);
    float d = v - m;
    float s2 = d * d;
    #pragma unroll
    for (int o = 16; o; o >>= 1) s2 += __shfl_xor_sync(~0u, s2, o);
    if ((j & 31) == 0) sh2[j >> 5] = s2;
    __syncthreads();
    float var = (sh2[0] + sh2[1] + sh2[2] + sh2[3]) * (1.0f/128.0f);
    y[row*D_ + j] = d * rsqrtf(var + 1e-5f) * w[j] + b[j];
}

// ---------------- generic C = act(A @ W^T + bias) [+ addin], tiled ----------
// A:(M,K) row-major, W:(N,K) row-major. BM=BN=64, BK=16, 256 thr, 4x4/thr.
// ACT: 0 none, 1 relu, 2 elu+1. SCATTER: write to y layout (t*B+b)*N+c.
template<int ACT, bool ADD, bool SCATTER>
__global__ void gemm_nt(const float* __restrict__ A,
                        const float* __restrict__ W,
                        const float* __restrict__ bias,
                        const float* __restrict__ addin,
                        float* __restrict__ C,
                        int M, int N, int K)
{
    __shared__ float As[16][64];
    __shared__ float Bs[16][64];
    int tid = threadIdx.x;
    int rowBase = blockIdx.x * 64;
    int colBase = blockIdx.y * 64;
    int tx = tid & 15, ty = tid >> 4;
    int lr = tid >> 2;          // 0..63
    int lk = (tid & 3) * 4;     // 0,4,8,12
    float acc[4][4] = {};
    for (int k0 = 0; k0 < K; k0 += 16) {
        float4 av = *(const float4*)(A + (size_t)(rowBase + lr)*K + k0 + lk);
        float4 bv = *(const float4*)(W + (size_t)(colBase + lr)*K + k0 + lk);
        As[lk+0][lr] = av.x; As[lk+1][lr] = av.y; As[lk+2][lr] = av.z; As[lk+3][lr] = av.w;
        Bs[lk+0][lr] = bv.x; Bs[lk+1][lr] = bv.y; Bs[lk+2][lr] = bv.z; Bs[lk+3][lr] = bv.w;
        __syncthreads();
        #pragma unroll
        for (int kk = 0; kk < 16; kk++) {
            float a[4], bb[4];
            #pragma unroll
            for (int i = 0; i < 4; i++) a[i]  = As[kk][ty*4 + i];
            #pragma unroll
            for (int j = 0; j < 4; j++) bb[j] = Bs[kk][tx*4 + j];
            #pragma unroll
            for (int i = 0; i < 4; i++)
                #pragma unroll
                for (int j = 0; j < 4; j++)
                    acc[i][j] += a[i] * bb[j];
        }
        __syncthreads();
    }
    #pragma unroll
    for (int i = 0; i < 4; i++) {
        int r = rowBase + ty*4 + i;
        #pragma unroll
        for (int j = 0; j < 4; j++) {
            int c = colBase + tx*4 + j;
            float v = acc[i][j] + (bias ? bias[c] : 0.0f);
            if (ACT == 1) v = fmaxf(v, 0.0f);
            if (ACT == 2) v = (v > 0.0f) ? v + 1.0f : expf(v);
            if (ADD) v += addin[(size_t)r*N + c];
            size_t oidx;
            if (SCATTER) { int t = r % T_; int bb2 = r / T_; oidx = ((size_t)t*B_ + bb2)*N + c; }
            else         { oidx = (size_t)r*N + c; }
            C[oidx] = v;
        }
    }
}

// ---------------- A = causal(Q @ K^T) per batch ------------------------------
__global__ void attnA_kernel(const float* __restrict__ Q,
                             const float* __restrict__ Km,
                             float* __restrict__ A)
{
    int b = blockIdx.z;
    int uBase = blockIdx.x * 64;
    int tBase = blockIdx.y * 64;
    float* Ab = A + (size_t)b * T_ * T_;
    int tid = threadIdx.x;
    int tx = tid & 15, ty = tid >> 4;
    if (uBase > tBase) {   // fully above diagonal -> zeros
        #pragma unroll
        for (int i = 0; i < 4; i++)
            #pragma unroll
            for (int j = 0; j < 4; j++)
                Ab[(size_t)(tBase + ty*4 + i)*T_ + uBase + tx*4 + j] = 0.0f;
        return;
    }
    const float* Qb = Q  + (size_t)b * T_ * D_;
    const float* Kb = Km + (size_t)b * T_ * D_;
    __shared__ float Qs[16][64], Ks[16][64];
    int lr = tid >> 2, lk = (tid & 3) * 4;
    float acc[4][4] = {};
    for (int k0 = 0; k0 < D_; k0 += 16) {
        float4 qv = *(const float4*)(Qb + (size_t)(tBase + lr)*D_ + k0 + lk);
        float4 kv = *(const float4*)(Kb + (size_t)(uBase + lr)*D_ + k0 + lk);
        Qs[lk+0][lr] = qv.x; Qs[lk+1][lr] = qv.y; Qs[lk+2][lr] = qv.z; Qs[lk+3][lr] = qv.w;
        Ks[lk+0][lr] = kv.x; Ks[lk+1][lr] = kv.y; Ks[lk+2][lr] = kv.z; Ks[lk+3][lr] = kv.w;
        __syncthreads();
        #pragma unroll
        for (int kk = 0; kk < 16; kk++) {
            float a[4], bb[4];
            #pragma unroll
            for (int i = 0; i < 4; i++) a[i]  = Qs[kk][ty*4 + i];
            #pragma unroll
            for (int j = 0; j < 4; j++) bb[j] = Ks[kk][tx*4 + j];
            #pragma unroll
            for (int i = 0; i < 4; i++)
                #pragma unroll
                for (int j = 0; j < 4; j++)
                    acc[i][j] += a[i] * bb[j];
        }
        __syncthreads();
    }
    #pragma unroll
    for (int i = 0; i < 4; i++) {
        int t = tBase + ty*4 + i;
        #pragma unroll
        for (int j = 0; j < 4; j++) {
            int u = uBase + tx*4 + j;
            Ab[(size_t)t*T_ + u] = (u <= t) ? acc[i][j] : 0.0f;
        }
    }
}

// ---------------- out = (A@V + Q@S0) / (rowsum(A) + Q.Z0 + 1e-5) -------------
// BM=64 rows(t), BN=128 cols(l), 256 thr, acc 4x8.
__global__ void attnO_kernel(const float* __restrict__ A,
                             const float* __restrict__ V,
                             const float* __restrict__ Q,
                             const float* __restrict__ state,
                             int layer,
                             float* __restrict__ O)
{
    int b = blockIdx.y;
    int tBase = blockIdx.x * 64;
    const float* Ab = A + (size_t)b * T_ * T_;
    const float* Vb = V + (size_t)b * T_ * D_;
    const float* Qb = Q + (size_t)b * T_ * D_;
    const float* S0 = state + (size_t)b * STROW + (size_t)layer * (D_*D_ + D_);
    const float* Z0 = S0 + D_*D_;
    __shared__ float As[16][64];
    __shared__ float Bs[16][128];
    __shared__ float den[64];
    __shared__ float z0s[16];
    int tid = threadIdx.x;
    int tx = tid & 15, ty = tid >> 4;
    int lr = tid >> 2, lk = (tid & 3) * 4;
    if (tid < 64) den[tid] = 0.0f;
    float acc[4][8] = {};
    // pass 1: A @ V  (K = 256), accumulate rowsum(A) into den
    for (int k0 = 0; k0 < T_; k0 += 16) {
        float4 av = *(const float4*)(Ab + (size_t)(tBase + lr)*T_ + k0 + lk);
        As[lk+0][lr] = av.x; As[lk+1][lr] = av.y; As[lk+2][lr] = av.z; As[lk+3][lr] = av.w;
        #pragma unroll
        for (int u = 0; u < 2; u++) {
            int lin = tid + u*256;
            int kk = lin >> 5, c4 = (lin & 31) * 4;
            *(float4*)&Bs[kk][c4] = *(const float4*)(Vb + (size_t)(k0 + kk)*D_ + c4);
        }
        __syncthreads();
        if (tid < 64) {
            float s = 0.0f;
            #pragma unroll
            for (int kk = 0; kk < 16; kk++) s += As[kk][tid];
            den[tid] += s;
        }
        #pragma unroll
        for (int kk = 0; kk < 16; kk++) {
            float a[4], bb[8];
            #pragma unroll
            for (int i = 0; i < 4; i++) a[i]  = As[kk][ty*4 + i];
            #pragma unroll
            for (int j = 0; j < 8; j++) bb[j] = Bs[kk][tx*8 + j];
            #pragma unroll
            for (int i = 0; i < 4; i++)
                #pragma unroll
                for (int j = 0; j < 8; j++)
                    acc[i][j] += a[i] * bb[j];
        }
        __syncthreads();
    }
    // pass 2: Q @ S0 (K = 128), accumulate Q.Z0 into den
    // NOTE: S0 is only 4-byte aligned (STROW=33025 is odd) -> scalar loads only.
    for (int k0 = 0; k0 < D_; k0 += 16) {
        float4 qv = *(const float4*)(Qb + (size_t)(tBase + lr)*D_ + k0 + lk);
        As[lk+0][lr] = qv.x; As[lk+1][lr] = qv.y; As[lk+2][lr] = qv.z; As[lk+3][lr] = qv.w;
        #pragma unroll
        for (int u = 0; u < 2; u++) {
            int lin = tid + u*256;
            int kk = lin >> 5, c4 = (lin & 31) * 4;
            const float* src = S0 + (size_t)(k0 + kk)*D_ + c4;
            Bs[kk][c4+0] = src[0];
            Bs[kk][c4+1] = src[1];
            Bs[kk][c4+2] = src[2];
            Bs[kk][c4+3] = src[3];
        }
        if (tid < 16) z0s[tid] = Z0[k0 + tid];
        __syncthreads();
        if (tid < 64) {
            float s = 0.0f;
            #pragma unroll
            for (int kk = 0; kk < 16; kk++) s += As[kk][tid] * z0s[kk];
            den[tid] += s;
        }
        #pragma unroll
        for (int kk = 0; kk < 16; kk++) {
            float a[4], bb[8];
            #pragma unroll
            for (int i = 0; i < 4; i++) a[i]  = As[kk][ty*4 + i];
            #pragma unroll
            for (int j = 0; j < 8; j++) bb[j] = Bs[kk][tx*8 + j];
            #pragma unroll
            for (int i = 0; i < 4; i++)
                #pragma unroll
                for (int j = 0; j < 8; j++)
                    acc[i][j] += a[i] * bb[j];
        }
        __syncthreads();
    }
    #pragma unroll
    for (int i = 0; i < 4; i++) {
        int t = tBase + ty*4 + i;
        float inv = 1.0f / (den[ty*4 + i] + 1e-5f);
        #pragma unroll
        for (int j = 0; j < 8; j++)
            O[((size_t)b*T_ + t)*D_ + tx*8 + j] = acc[i][j] * inv;
    }
}

// ---------------- Sl = S0 + K^T@V ; Zl = Z0 + colsum(K) ----------------------
__global__ void state_kernel(const float* __restrict__ Km,
                             const float* __restrict__ V,
                             const float* __restrict__ state,
                             int layer,
                             float* __restrict__ stout)
{
    int b = blockIdx.z;
    int iBase = blockIdx.x * 64;
    int lBase = blockIdx.y * 64;
    const float* Kb = Km + (size_t)b * T_ * D_;
    const float* Vb = V  + (size_t)b * T_ * D_;
    __shared__ float Ks[16][64], Vs[16][64];
    __shared__ float zsum[64];
    int tid = threadIdx.x;
    int tx = tid & 15, ty = tid >> 4;
    int lkk = tid >> 4, lc = (tid & 15) * 4;
    if (tid < 64) zsum[tid] = 0.0f;
    float acc[4][4] = {};
    for (int k0 = 0; k0 < T_; k0 += 16) {
        *(float4*)&Ks[lkk][lc] = *(const float4*)(Kb + (size_t)(k0 + lkk)*D_ + iBase + lc);
        *(float4*)&Vs[lkk][lc] = *(const float4*)(Vb + (size_t)(k0 + lkk)*D_ + lBase + lc);
        __syncthreads();
        if (blockIdx.y == 0 && tid < 64) {
            float s = 0.0f;
            #pragma unroll
            for (int kk = 0; kk < 16; kk++) s += Ks[kk][tid];
            zsum[tid] += s;
        }
        #pragma unroll
        for (int kk = 0; kk < 16; kk++) {
            float a[4], bb[4];
            #pragma unroll
            for (int i = 0; i < 4; i++) a[i]  = Ks[kk][ty*4 + i];
            #pragma unroll
            for (int j = 0; j < 4; j++) bb[j] = Vs[kk][tx*4 + j];
            #pragma unroll
            for (int i = 0; i < 4; i++)
                #pragma unroll
                for (int j = 0; j < 4; j++)
                    acc[i][j] += a[i] * bb[j];
        }
        __syncthreads();
    }
    const float* S0 = state + (size_t)b * STROW + (size_t)layer * (D_*D_ + D_);
    float* dst = stout + (size_t)b * STROW + (size_t)layer * (D_*D_ + D_);
    #pragma unroll
    for (int i = 0; i < 4; i++) {
        int ii = iBase + ty*4 + i;
        #pragma unroll
        for (int j = 0; j < 4; j++) {
            int ll = lBase + tx*4 + j;
            dst[(size_t)ii*D_ + ll] = acc[i][j] + S0[(size_t)ii*D_ + ll];
        }
    }
    if (blockIdx.y == 0 && tid < 64) {
        int ii = iBase + tid;
        dst[D_*D_ + ii] = zsum[tid] + S0[D_*D_ + ii];
    }
}

// ---------------------------------------------------------------------------
extern "C" void kernel_launch(void* const* d_in, const int* in_sizes, int n_in,
                              void* d_out, int out_size)
{
    const float* z     = (const float*)d_in[0];
    const float* state = (const float*)d_in[1];
    const float* Wk    = (const float*)d_in[2];
    const float* Wq    = (const float*)d_in[3];
    const float* Wv    = (const float*)d_in[4];
    const float* ln_w  = (const float*)d_in[5];
    const float* ln_b  = (const float*)d_in[6];
    const float* ff_w1 = (const float*)d_in[7];
    const float* ff_b1 = (const float*)d_in[8];
    const float* ff_w2 = (const float*)d_in[9];
    const float* ff_b2 = (const float*)d_in[10];
    const float* sc_w  = (const float*)d_in[11];
    const float* sc_b  = (const float*)d_in[12];
    const float* um_w  = (const float*)d_in[13];
    const float* um_b  = (const float*)d_in[14];
    float* out = (float*)d_out;
    float* stout = out + YSZ;

    float *x, *xln, *Q, *K, *V, *A, *att, *h1, *t2;
    cudaGetSymbolAddress((void**)&x,   g_x);
    cudaGetSymbolAddress((void**)&xln, g_xln);
    cudaGetSymbolAddress((void**)&Q,   g_Q);
    cudaGetSymbolAddress((void**)&K,   g_K);
    cudaGetSymbolAddress((void**)&V,   g_V);
    cudaGetSymbolAddress((void**)&A,   g_A);
    cudaGetSymbolAddress((void**)&att, g_att);
    cudaGetSymbolAddress((void**)&h1,  g_h1);
    cudaGetSymbolAddress((void**)&t2,  g_t2);

    rotate_kernel<<<(B_*T_*64 + 255)/256, 256>>>(z, state, x, stout);

    dim3 g(ROWS/64, D_/64);
    for (int l = 0; l < L_; l++) {
        ln_kernel<<<ROWS, 128>>>(x, ln_w + l*D_, ln_b + l*D_, xln);
        gemm_nt<2,false,false><<<g,256>>>(xln, Wq + (size_t)l*D_*D_, nullptr, nullptr, Q, ROWS, D_, D_);
        gemm_nt<2,false,false><<<g,256>>>(xln, Wk + (size_t)l*D_*D_, nullptr, nullptr, K, ROWS, D_, D_);
        gemm_nt<0,false,false><<<g,256>>>(xln, Wv + (size_t)l*D_*D_, nullptr, nullptr, V, ROWS, D_, D_);
        attnA_kernel<<<dim3(4,4,8), 256>>>(Q, K, A);
        attnO_kernel<<<dim3(4,8), 256>>>(A, V, Q, state, l, att);
        state_kernel<<<dim3(2,2,8), 256>>>(K, V, state, l, stout);
        gemm_nt<1,false,false><<<g,256>>>(att, ff_w1 + (size_t)l*D_*D_, ff_b1 + l*D_, nullptr, h1, ROWS, D_, D_);
        gemm_nt<1,false,false><<<g,256>>>(h1,  ff_w2 + (size_t)l*D_*D_, ff_b2 + l*D_, nullptr, t2, ROWS, D_, D_);
        gemm_nt<0,true ,false><<<g,256>>>(xln, sc_w  + (size_t)l*D_*D_, sc_b  + l*D_, t2, x, ROWS, D_, D_);
    }
    gemm_nt<0,false,true><<<g,256>>>(x, um_w, um_b, nullptr, out, ROWS, D_, D_);
}